// round 16
// baseline (speedup 1.0000x reference)
#include <cuda_runtime.h>
#include <cuda_bf16.h>
#include <cuda_fp16.h>
#include <math.h>
#include <stdint.h>

#define NN 50000
#define EE 800000
#define FIN 128
#define HC 256      // HEADS*HID = 4*64
#define HEADS 4
#define HID 64
#define C2 64       // CLASSES
#define ETOT (EE + NN)
#define NEG_ATT 0.2f
#define NEG_ACT 0.01f
#define BN_EPS 1e-5f

// ---------------- scratch (device globals; no allocation allowed) ------------
__device__ int   g_counts[NN];
__device__ int   g_incl[NN];
__device__ int   g_bsum[64];
__device__ int   g_offs[NN + 1];
__device__ int   g_cursor[NN];
__device__ int   g_csr[ETOT];

__device__ __half2 g_h1h[NN * (HC / 2)];   // x @ W1 as fp16 pairs (gather input)
__device__ __half2 g_h2h[NN * (C2 / 2)];   // hn @ W2 as fp16 pairs
__device__ __half2 g_agg1h[NN * (HC / 2)]; // GAT1 output (+b1), fp16
__device__ float g_as1[NN * HEADS];
__device__ float g_ad1[NN * HEADS];
__device__ float g_bnsum[HC];
__device__ float g_bnsq[HC];
__device__ float g_scale[HC];
__device__ float g_shift[HC];
__device__ float g_as2[NN];
__device__ float g_ad2[NN];
__device__ int   g_bncnt;

// W fragments, fragment-linear: W1: [nhalf(2)][khalf(2)][nt(16)][kt(4)][lane(32)] uint4
__device__ uint4 g_wf1[2 * 2 * 16 * 4 * 32];   // 8192
// W2: [kq(4)][nt(8)][kt(4)][lane(32)] uint4
__device__ uint4 g_wf2[4 * 8 * 4 * 32];        // 4096

__device__ __forceinline__ float lrelu(float v, float s) { return v > 0.f ? v : s * v; }

__device__ __forceinline__ uint32_t pack_bf(float a, float b) {
    __nv_bfloat16 ba = __float2bfloat16(a);
    __nv_bfloat16 bb = __float2bfloat16(b);
    uint16_t ua = *(uint16_t*)&ba;
    uint16_t ub = *(uint16_t*)&bb;
    return (uint32_t)ua | ((uint32_t)ub << 16);
}

// split a float2 into bf16 hi pair + bf16 lo-residual pair
__device__ __forceinline__ void split2(float2 u, uint32_t& hi, uint32_t& lo) {
    float hx = __bfloat162float(__float2bfloat16(u.x));
    float hy = __bfloat162float(__float2bfloat16(u.y));
    hi = pack_bf(hx, hy);
    lo = pack_bf(u.x - hx, u.y - hy);
}

__device__ __forceinline__ void mma16816(float* c, uint32_t a0, uint32_t a1,
                                         uint32_t a2, uint32_t a3,
                                         uint32_t b0, uint32_t b1) {
    asm volatile(
        "mma.sync.aligned.m16n8k16.row.col.f32.bf16.bf16.f32 "
        "{%0,%1,%2,%3}, {%4,%5,%6,%7}, {%8,%9}, {%0,%1,%2,%3};\n"
        : "+f"(c[0]), "+f"(c[1]), "+f"(c[2]), "+f"(c[3])
        : "r"(a0), "r"(a1), "r"(a2), "r"(a3), "r"(b0), "r"(b1));
}

__device__ __forceinline__ float4 e4(float4 a, float4 ad) {
    float4 e;
    e.x = __expf(lrelu(a.x + ad.x, NEG_ATT));
    e.y = __expf(lrelu(a.y + ad.y, NEG_ATT));
    e.z = __expf(lrelu(a.z + ad.z, NEG_ATT));
    e.w = __expf(lrelu(a.w + ad.w, NEG_ATT));
    return e;
}

// ---------------- CSR build --------------------------------------------------
__global__ void k_init() {
    int i = blockIdx.x * blockDim.x + threadIdx.x;
    if (i < NN) g_counts[i] = 1;          // self loop pre-counted
    if (i < HC) { g_bnsum[i] = 0.f; g_bnsq[i] = 0.f; }
    if (i == 0) g_bncnt = 0;
}

__global__ void k_hist(const int4* __restrict__ dst4) {   // EE/4 elements
    int e = blockIdx.x * blockDim.x + threadIdx.x;
    if (e < EE / 4) {
        int4 d = dst4[e];
        atomicAdd(&g_counts[d.x], 1);
        atomicAdd(&g_counts[d.y], 1);
        atomicAdd(&g_counts[d.z], 1);
        atomicAdd(&g_counts[d.w], 1);
    }
}

__global__ void k_scan_block() {   // grid 49, 1024 threads
    __shared__ int sd[1024];
    int t = threadIdx.x;
    int i = blockIdx.x * 1024 + t;
    int v = (i < NN) ? g_counts[i] : 0;
    sd[t] = v;
    __syncthreads();
    for (int off = 1; off < 1024; off <<= 1) {
        int add = (t >= off) ? sd[t - off] : 0;
        __syncthreads();
        sd[t] += add;
        __syncthreads();
    }
    if (i < NN) g_incl[i] = sd[t];
    if (t == 1023) g_bsum[blockIdx.x] = sd[1023];
}

// finish scan (warp-parallel prefix), insert self-loop at slot 0, set cursor
__global__ void k_scan_finish() {
    __shared__ int s_pref;
    int b = blockIdx.x;
    int t = threadIdx.x;
    int i = b * 256 + t;
    int chunk = b >> 2;        // all 256 indices share i>>10; chunk <= 48
    if (t < 32) {
        int v = (t < chunk) ? g_bsum[t] : 0;
        if (t + 32 < chunk) v += g_bsum[t + 32];
#pragma unroll
        for (int off = 16; off > 0; off >>= 1)
            v += __shfl_xor_sync(0xffffffffu, v, off);
        if (t == 0) s_pref = v;
    }
    __syncthreads();
    if (i < NN) {
        int incl = g_incl[i] + s_pref;
        g_offs[i + 1] = incl;
        int start = incl - g_counts[i];
        g_csr[start] = i;          // self loop occupies first slot
        g_cursor[i] = start + 1;
        if (i == 0) g_offs[0] = 0;
    }
}

__global__ void k_scatter(const int4* __restrict__ src4, const int4* __restrict__ dst4) {
    int e = blockIdx.x * blockDim.x + threadIdx.x;
    if (e < EE / 4) {
        int4 s = src4[e];
        int4 d = dst4[e];
        g_csr[atomicAdd(&g_cursor[d.x], 1)] = s.x;
        g_csr[atomicAdd(&g_cursor[d.y], 1)] = s.y;
        g_csr[atomicAdd(&g_cursor[d.z], 1)] = s.z;
        g_csr[atomicAdd(&g_cursor[d.w], 1)] = s.w;
    }
}

// ---------------- W fragment prep (both weights, one launch) -----------------
__global__ void k_prep_w(const float* __restrict__ W1f, const float* __restrict__ W2f) {
    int i = blockIdx.x * blockDim.x + threadIdx.x;
    if (i < 8192) {
        int lane = i & 31;
        int kt = (i >> 5) & 3;
        int nt = (i >> 7) & 15;
        int kh = (i >> 11) & 1;
        int nh = (i >> 12) & 1;
        int g = lane >> 2, q = lane & 3;
        int k = kh * 64 + kt * 16 + 2 * q;
        int n = nh * 128 + nt * 8 + g;
        float w00 = W1f[k * HC + n];
        float w01 = W1f[(k + 1) * HC + n];
        float w10 = W1f[(k + 8) * HC + n];
        float w11 = W1f[(k + 9) * HC + n];
        float h00 = __bfloat162float(__float2bfloat16(w00));
        float h01 = __bfloat162float(__float2bfloat16(w01));
        float h10 = __bfloat162float(__float2bfloat16(w10));
        float h11 = __bfloat162float(__float2bfloat16(w11));
        g_wf1[i] = make_uint4(pack_bf(h00, h01), pack_bf(h10, h11),
                              pack_bf(w00 - h00, w01 - h01), pack_bf(w10 - h10, w11 - h11));
    } else if (i < 8192 + 4096) {
        int j = i - 8192;
        int lane = j & 31;
        int kt = (j >> 5) & 3;
        int nt = (j >> 7) & 7;
        int kq = (j >> 10) & 3;
        int g = lane >> 2, q = lane & 3;
        int k = kq * 64 + kt * 16 + 2 * q;
        int n = nt * 8 + g;
        float w00 = W2f[k * C2 + n];
        float w01 = W2f[(k + 1) * C2 + n];
        float w10 = W2f[(k + 8) * C2 + n];
        float w11 = W2f[(k + 9) * C2 + n];
        float h00 = __bfloat162float(__float2bfloat16(w00));
        float h01 = __bfloat162float(__float2bfloat16(w01));
        float h10 = __bfloat162float(__float2bfloat16(w10));
        float h11 = __bfloat162float(__float2bfloat16(w11));
        g_wf2[j] = make_uint4(pack_bf(h00, h01), pack_bf(h10, h11),
                              pack_bf(w00 - h00, w01 - h01), pack_bf(w10 - h10, w11 - h11));
    }
}

// ---------------- GEMM1: h1 = x @ W1, fp16 store + alpha1 epilogue ----------
// grid (391, 2), 256 threads. Warp w: rows [bx*128+w*16, +16), cols nh*128..+128
__global__ __launch_bounds__(256) void k_gemm1(const float* __restrict__ x,
                                               const float* __restrict__ a_src,
                                               const float* __restrict__ a_dst) {
    __shared__ uint4 bs[16][4][32];    // 32 KB
    int t = threadIdx.x;
    int w = t >> 5, lane = t & 31;
    int g = lane >> 2, q = lane & 3;
    int m0 = blockIdx.x * 128 + w * 16 + g;
    int m1 = m0 + 8;
    bool v0 = m0 < NN, v1 = m1 < NN;
    int nh = blockIdx.y;

    float acc[16][4];
#pragma unroll
    for (int nt = 0; nt < 16; nt++)
#pragma unroll
        for (int r = 0; r < 4; r++) acc[nt][r] = 0.f;

    for (int kh = 0; kh < 2; kh++) {
        const uint4* srcw = g_wf1 + (nh * 2 + kh) * 2048;
        for (int i = t; i < 2048; i += 256) ((uint4*)bs)[i] = srcw[i];
        __syncthreads();
#pragma unroll
        for (int kt = 0; kt < 4; kt++) {
            int kk = kh * 64 + kt * 16 + 2 * q;
            uint32_t ah0 = 0, ah1 = 0, ah2 = 0, ah3 = 0;
            uint32_t al0 = 0, al1 = 0, al2 = 0, al3 = 0;
            if (v0) {
                split2(*(const float2*)&x[m0 * FIN + kk], ah0, al0);
                split2(*(const float2*)&x[m0 * FIN + kk + 8], ah2, al2);
            }
            if (v1) {
                split2(*(const float2*)&x[m1 * FIN + kk], ah1, al1);
                split2(*(const float2*)&x[m1 * FIN + kk + 8], ah3, al3);
            }
#pragma unroll
            for (int nt = 0; nt < 16; nt++) {
                uint4 b = bs[nt][kt][lane];
                mma16816(acc[nt], ah0, ah1, ah2, ah3, b.x, b.y);  // hi*hi
                mma16816(acc[nt], ah0, ah1, ah2, ah3, b.z, b.w);  // hi*lo
                mma16816(acc[nt], al0, al1, al2, al3, b.x, b.y);  // lo*hi
            }
        }
        __syncthreads();
    }
    int nbase = nh * 128;
#pragma unroll
    for (int nt = 0; nt < 16; nt++) {
        int hidx = (nbase >> 1) + nt * 4 + q;
        if (v0) g_h1h[m0 * (HC / 2) + hidx] = __float22half2_rn(make_float2(acc[nt][0], acc[nt][1]));
        if (v1) g_h1h[m1 * (HC / 2) + hidx] = __float22half2_rn(make_float2(acc[nt][2], acc[nt][3]));
    }

    // fused alpha: per-head dot with a_src / a_dst (heads align with nt groups)
    float ps[2][2] = {{0.f, 0.f}, {0.f, 0.f}};
    float pd[2][2] = {{0.f, 0.f}, {0.f, 0.f}};
#pragma unroll
    for (int nt = 0; nt < 16; nt++) {
        int hl = nt >> 3;
        int c0 = nbase + nt * 8 + 2 * q;
        float s0 = a_src[c0], s1 = a_src[c0 + 1];
        float d0 = a_dst[c0], d1 = a_dst[c0 + 1];
        ps[hl][0] += acc[nt][0] * s0 + acc[nt][1] * s1;
        pd[hl][0] += acc[nt][0] * d0 + acc[nt][1] * d1;
        ps[hl][1] += acc[nt][2] * s0 + acc[nt][3] * s1;
        pd[hl][1] += acc[nt][2] * d0 + acc[nt][3] * d1;
    }
#pragma unroll
    for (int off = 1; off <= 2; off <<= 1) {
#pragma unroll
        for (int hl = 0; hl < 2; hl++) {
            ps[hl][0] += __shfl_xor_sync(0xffffffffu, ps[hl][0], off);
            ps[hl][1] += __shfl_xor_sync(0xffffffffu, ps[hl][1], off);
            pd[hl][0] += __shfl_xor_sync(0xffffffffu, pd[hl][0], off);
            pd[hl][1] += __shfl_xor_sync(0xffffffffu, pd[hl][1], off);
        }
    }
    if (q == 0) {
#pragma unroll
        for (int hl = 0; hl < 2; hl++) {
            int gh = nh * 2 + hl;
            if (v0) { g_as1[m0 * 4 + gh] = ps[hl][0]; g_ad1[m0 * 4 + gh] = pd[hl][0]; }
            if (v1) { g_as1[m1 * 4 + gh] = ps[hl][1]; g_ad1[m1 * 4 + gh] = pd[hl][1]; }
        }
    }
}

// ---------------- GAT layer 1: warp/node fused softmax + aggregate -----------
// Each warp handles one node; lane owns 8 channels. Per-warp smem staging of
// edge idx + alpha (no block barriers; __syncwarp only). 4-edge unrolled gather.
__global__ __launch_bounds__(128) void k_gat1(const float* __restrict__ b1) {
    __shared__ int    s_idx[4][32];
    __shared__ float4 s_al4[4][32];
    int w = threadIdx.x >> 5, lane = threadIdx.x & 31;
    int n = blockIdx.x * 4 + w;
    if (n >= NN) return;                 // uniform per warp
    int base = g_offs[n], deg = g_offs[n + 1] - base;
    float4 ad = ((const float4*)g_ad1)[n];
    int myh = lane >> 3;                 // head for channels lane*8..lane*8+7

    // softmax phase: register-cached exp for deg<=128
    int ic[4];
    float4 ec[4];
    float4 sm = make_float4(0.f, 0.f, 0.f, 0.f);
#pragma unroll
    for (int c = 0; c < 4; c++) {
        int j = lane + c * 32;
        ic[c] = 0;
        ec[c] = make_float4(0.f, 0.f, 0.f, 0.f);
        if (j < deg) {
            ic[c] = g_csr[base + j];
            ec[c] = e4(((const float4*)g_as1)[ic[c]], ad);
            sm.x += ec[c].x; sm.y += ec[c].y; sm.z += ec[c].z; sm.w += ec[c].w;
        }
    }
    for (int j = lane + 128; j < deg; j += 32) {   // rare tail
        int s = g_csr[base + j];
        float4 e = e4(((const float4*)g_as1)[s], ad);
        sm.x += e.x; sm.y += e.y; sm.z += e.z; sm.w += e.w;
    }
#pragma unroll
    for (int off = 16; off > 0; off >>= 1) {
        sm.x += __shfl_xor_sync(0xffffffffu, sm.x, off);
        sm.y += __shfl_xor_sync(0xffffffffu, sm.y, off);
        sm.z += __shfl_xor_sync(0xffffffffu, sm.z, off);
        sm.w += __shfl_xor_sync(0xffffffffu, sm.w, off);
    }
    float4 rv = make_float4(1.f / sm.x, 1.f / sm.y, 1.f / sm.z, 1.f / sm.w);

    const uint4* h1u4 = (const uint4*)g_h1h;       // 32 uint4 per node row
    float acc[8];
#pragma unroll
    for (int k = 0; k < 8; k++) acc[k] = 0.f;

    const float* alw = (const float*)&s_al4[w][0]; // 32 float4 as flat floats

    for (int cb = 0, c = 0; cb < deg; cb += 32, c++) {
        int len = min(32, deg - cb);
        int myidx;
        float4 mya;
        if (c < 4) {
            myidx = ic[c];
            mya = make_float4(ec[c].x * rv.x, ec[c].y * rv.y,
                              ec[c].z * rv.z, ec[c].w * rv.w);
        } else {
            myidx = 0; mya = make_float4(0.f, 0.f, 0.f, 0.f);
            if (lane < len) {
                myidx = g_csr[base + cb + lane];
                float4 e = e4(((const float4*)g_as1)[myidx], ad);
                mya = make_float4(e.x * rv.x, e.y * rv.y, e.z * rv.z, e.w * rv.w);
            }
        }
        __syncwarp();
        s_idx[w][lane] = myidx;
        s_al4[w][lane] = mya;
        __syncwarp();

        int j = 0;
        for (; j + 4 <= len; j += 4) {
            int s0 = s_idx[w][j + 0];
            int s1 = s_idx[w][j + 1];
            int s2 = s_idx[w][j + 2];
            int s3 = s_idx[w][j + 3];
            float aa0 = alw[(j + 0) * 4 + myh];
            float aa1 = alw[(j + 1) * 4 + myh];
            float aa2 = alw[(j + 2) * 4 + myh];
            float aa3 = alw[(j + 3) * 4 + myh];
            uint4 v0 = h1u4[s0 * 32 + lane];
            uint4 v1 = h1u4[s1 * 32 + lane];
            uint4 v2 = h1u4[s2 * 32 + lane];
            uint4 v3 = h1u4[s3 * 32 + lane];
            float2 p;
            p = __half22float2(*(__half2*)&v0.x); acc[0] = fmaf(aa0, p.x, acc[0]); acc[1] = fmaf(aa0, p.y, acc[1]);
            p = __half22float2(*(__half2*)&v0.y); acc[2] = fmaf(aa0, p.x, acc[2]); acc[3] = fmaf(aa0, p.y, acc[3]);
            p = __half22float2(*(__half2*)&v0.z); acc[4] = fmaf(aa0, p.x, acc[4]); acc[5] = fmaf(aa0, p.y, acc[5]);
            p = __half22float2(*(__half2*)&v0.w); acc[6] = fmaf(aa0, p.x, acc[6]); acc[7] = fmaf(aa0, p.y, acc[7]);
            p = __half22float2(*(__half2*)&v1.x); acc[0] = fmaf(aa1, p.x, acc[0]); acc[1] = fmaf(aa1, p.y, acc[1]);
            p = __half22float2(*(__half2*)&v1.y); acc[2] = fmaf(aa1, p.x, acc[2]); acc[3] = fmaf(aa1, p.y, acc[3]);
            p = __half22float2(*(__half2*)&v1.z); acc[4] = fmaf(aa1, p.x, acc[4]); acc[5] = fmaf(aa1, p.y, acc[5]);
            p = __half22float2(*(__half2*)&v1.w); acc[6] = fmaf(aa1, p.x, acc[6]); acc[7] = fmaf(aa1, p.y, acc[7]);
            p = __half22float2(*(__half2*)&v2.x); acc[0] = fmaf(aa2, p.x, acc[0]); acc[1] = fmaf(aa2, p.y, acc[1]);
            p = __half22float2(*(__half2*)&v2.y); acc[2] = fmaf(aa2, p.x, acc[2]); acc[3] = fmaf(aa2, p.y, acc[3]);
            p = __half22float2(*(__half2*)&v2.z); acc[4] = fmaf(aa2, p.x, acc[4]); acc[5] = fmaf(aa2, p.y, acc[5]);
            p = __half22float2(*(__half2*)&v2.w); acc[6] = fmaf(aa2, p.x, acc[6]); acc[7] = fmaf(aa2, p.y, acc[7]);
            p = __half22float2(*(__half2*)&v3.x); acc[0] = fmaf(aa3, p.x, acc[0]); acc[1] = fmaf(aa3, p.y, acc[1]);
            p = __half22float2(*(__half2*)&v3.y); acc[2] = fmaf(aa3, p.x, acc[2]); acc[3] = fmaf(aa3, p.y, acc[3]);
            p = __half22float2(*(__half2*)&v3.z); acc[4] = fmaf(aa3, p.x, acc[4]); acc[5] = fmaf(aa3, p.y, acc[5]);
            p = __half22float2(*(__half2*)&v3.w); acc[6] = fmaf(aa3, p.x, acc[6]); acc[7] = fmaf(aa3, p.y, acc[7]);
        }
        for (; j < len; j++) {
            int s0 = s_idx[w][j];
            float aa0 = alw[j * 4 + myh];
            uint4 v0 = h1u4[s0 * 32 + lane];
            float2 p;
            p = __half22float2(*(__half2*)&v0.x); acc[0] = fmaf(aa0, p.x, acc[0]); acc[1] = fmaf(aa0, p.y, acc[1]);
            p = __half22float2(*(__half2*)&v0.y); acc[2] = fmaf(aa0, p.x, acc[2]); acc[3] = fmaf(aa0, p.y, acc[3]);
            p = __half22float2(*(__half2*)&v0.z); acc[4] = fmaf(aa0, p.x, acc[4]); acc[5] = fmaf(aa0, p.y, acc[5]);
            p = __half22float2(*(__half2*)&v0.w); acc[6] = fmaf(aa0, p.x, acc[6]); acc[7] = fmaf(aa0, p.y, acc[7]);
        }
    }

    // bias + fp16 store (one uint4 = 4 half2 per lane)
    int cbase = lane * 8;
    __half2 o[4];
#pragma unroll
    for (int k = 0; k < 4; k++) {
        float2 bb = *(const float2*)&b1[cbase + 2 * k];
        o[k] = __float22half2_rn(make_float2(acc[2 * k] + bb.x, acc[2 * k + 1] + bb.y));
    }
    ((uint4*)g_agg1h)[n * 32 + lane] = *(uint4*)o;
}

// ---------------- BatchNorm: partial sums + fused finalize -------------------
__global__ __launch_bounds__(128) void k_bn(const float* __restrict__ gamma,
                                            const float* __restrict__ beta) {
    int t = threadIdx.x;                 // half2 column t → channels 2t, 2t+1
    int b = blockIdx.x;
    const int NBLK = 256;
    const int RPB = (NN + NBLK - 1) / NBLK;  // 196
    int rs = b * RPB, re = min(NN, rs + RPB);
    float sx = 0.f, sy = 0.f, qx = 0.f, qy = 0.f;
    for (int r = rs; r < re; r++) {
        float2 v = __half22float2(g_agg1h[r * (HC / 2) + t]);
        sx += v.x; sy += v.y;
        qx = fmaf(v.x, v.x, qx); qy = fmaf(v.y, v.y, qy);
    }
    atomicAdd(&g_bnsum[2 * t], sx);
    atomicAdd(&g_bnsum[2 * t + 1], sy);
    atomicAdd(&g_bnsq[2 * t], qx);
    atomicAdd(&g_bnsq[2 * t + 1], qy);
    __threadfence();
    __shared__ int s_last;
    __syncthreads();
    if (t == 0) s_last = (atomicAdd(&g_bncnt, 1) == NBLK - 1);
    __syncthreads();
    if (s_last) {
#pragma unroll
        for (int u = 0; u < 2; u++) {
            int c = 2 * t + u;
            float mean = g_bnsum[c] / (float)NN;
            float var = g_bnsq[c] / (float)NN - mean * mean;
            float rstd = rsqrtf(var + BN_EPS);
            float sc = gamma[c] * rstd;
            g_scale[c] = sc;
            g_shift[c] = beta[c] - mean * sc;
        }
    }
}

// ---------------- GEMM2: fused BN+leaky+split load, fp16 store, alpha2 -------
// grid 391, 256 threads. Warp w: rows [bx*128+w*16, +16), all 64 cols.
__global__ __launch_bounds__(256) void k_gemm2(const float* __restrict__ a_src,
                                               const float* __restrict__ a_dst) {
    __shared__ uint4 bs[8][4][32];     // 16 KB
    __shared__ float s_sc[HC], s_sh[HC];
    int t = threadIdx.x;
    int w = t >> 5, lane = t & 31;
    int g = lane >> 2, q = lane & 3;
    int m0 = blockIdx.x * 128 + w * 16 + g;
    int m1 = m0 + 8;
    bool v0 = m0 < NN, v1 = m1 < NN;
    for (int i = t; i < HC; i += 256) { s_sc[i] = g_scale[i]; s_sh[i] = g_shift[i]; }

    float acc[8][4];
#pragma unroll
    for (int nt = 0; nt < 8; nt++)
#pragma unroll
        for (int r = 0; r < 4; r++) acc[nt][r] = 0.f;

    for (int kq = 0; kq < 4; kq++) {
        const uint4* srcw = g_wf2 + kq * 1024;
        for (int i = t; i < 1024; i += 256) ((uint4*)bs)[i] = srcw[i];
        __syncthreads();
#pragma unroll
        for (int kt = 0; kt < 4; kt++) {
            int kk = kq * 64 + kt * 16 + 2 * q;
            float sc0 = s_sc[kk], sh0 = s_sh[kk];
            float sc1 = s_sc[kk + 1], sh1 = s_sh[kk + 1];
            float sc8 = s_sc[kk + 8], sh8 = s_sh[kk + 8];
            float sc9 = s_sc[kk + 9], sh9 = s_sh[kk + 9];
            uint32_t ah0 = 0, ah1 = 0, ah2 = 0, ah3 = 0;
            uint32_t al0 = 0, al1 = 0, al2 = 0, al3 = 0;
            if (v0) {
                float2 u = __half22float2(g_agg1h[m0 * (HC / 2) + (kk >> 1)]);
                float2 v = __half22float2(g_agg1h[m0 * (HC / 2) + ((kk + 8) >> 1)]);
                u.x = lrelu(fmaf(sc0, u.x, sh0), NEG_ACT);
                u.y = lrelu(fmaf(sc1, u.y, sh1), NEG_ACT);
                v.x = lrelu(fmaf(sc8, v.x, sh8), NEG_ACT);
                v.y = lrelu(fmaf(sc9, v.y, sh9), NEG_ACT);
                split2(u, ah0, al0);
                split2(v, ah2, al2);
            }
            if (v1) {
                float2 u = __half22float2(g_agg1h[m1 * (HC / 2) + (kk >> 1)]);
                float2 v = __half22float2(g_agg1h[m1 * (HC / 2) + ((kk + 8) >> 1)]);
                u.x = lrelu(fmaf(sc0, u.x, sh0), NEG_ACT);
                u.y = lrelu(fmaf(sc1, u.y, sh1), NEG_ACT);
                v.x = lrelu(fmaf(sc8, v.x, sh8), NEG_ACT);
                v.y = lrelu(fmaf(sc9, v.y, sh9), NEG_ACT);
                split2(u, ah1, al1);
                split2(v, ah3, al3);
            }
#pragma unroll
            for (int nt = 0; nt < 8; nt++) {
                uint4 b = bs[nt][kt][lane];
                mma16816(acc[nt], ah0, ah1, ah2, ah3, b.x, b.y);
                mma16816(acc[nt], ah0, ah1, ah2, ah3, b.z, b.w);
                mma16816(acc[nt], al0, al1, al2, al3, b.x, b.y);
            }
        }
        __syncthreads();
    }
#pragma unroll
    for (int nt = 0; nt < 8; nt++) {
        int hidx = nt * 4 + q;
        if (v0) g_h2h[m0 * (C2 / 2) + hidx] = __float22half2_rn(make_float2(acc[nt][0], acc[nt][1]));
        if (v1) g_h2h[m1 * (C2 / 2) + hidx] = __float22half2_rn(make_float2(acc[nt][2], acc[nt][3]));
    }

    // fused alpha2 (single head over all 64 cols)
    float ps0 = 0.f, ps1 = 0.f, pd0 = 0.f, pd1 = 0.f;
#pragma unroll
    for (int nt = 0; nt < 8; nt++) {
        int c0 = nt * 8 + 2 * q;
        float s0 = a_src[c0], s1 = a_src[c0 + 1];
        float d0 = a_dst[c0], d1 = a_dst[c0 + 1];
        ps0 += acc[nt][0] * s0 + acc[nt][1] * s1;
        pd0 += acc[nt][0] * d0 + acc[nt][1] * d1;
        ps1 += acc[nt][2] * s0 + acc[nt][3] * s1;
        pd1 += acc[nt][2] * d0 + acc[nt][3] * d1;
    }
#pragma unroll
    for (int off = 1; off <= 2; off <<= 1) {
        ps0 += __shfl_xor_sync(0xffffffffu, ps0, off);
        ps1 += __shfl_xor_sync(0xffffffffu, ps1, off);
        pd0 += __shfl_xor_sync(0xffffffffu, pd0, off);
        pd1 += __shfl_xor_sync(0xffffffffu, pd1, off);
    }
    if (q == 0) {
        if (v0) { g_as2[m0] = ps0; g_ad2[m0] = pd0; }
        if (v1) { g_as2[m1] = ps1; g_ad2[m1] = pd1; }
    }
}

// ---------------- GAT layer 2: warp/node, no-max softmax, reg cache → out ----
__global__ __launch_bounds__(128) void k_gat2(const float* __restrict__ b2,
                                              float* __restrict__ out) {
    int w = threadIdx.x >> 5, lane = threadIdx.x & 31;
    int n = blockIdx.x * 4 + w;
    if (n >= NN) return;
    int base = g_offs[n], deg = g_offs[n + 1] - base;
    float ad = g_ad2[n];

    int ic[4];
    float en[4];
    float sm = 0.f;
#pragma unroll
    for (int c = 0; c < 4; c++) {
        int j = lane + c * 32;
        ic[c] = 0; en[c] = 0.f;
        if (j < deg) {
            ic[c] = g_csr[base + j];
            en[c] = __expf(lrelu(g_as2[ic[c]] + ad, NEG_ATT));
            sm += en[c];
        }
    }
    for (int j = lane + 128; j < deg; j += 32)     // rare tail
        sm += __expf(lrelu(g_as2[g_csr[base + j]] + ad, NEG_ATT));
#pragma unroll
    for (int off = 16; off > 0; off >>= 1)
        sm += __shfl_xor_sync(0xffffffffu, sm, off);
    float ri = 1.f / sm;

    float ax = 0.f, ay = 0.f;
    for (int cb = 0, c = 0; cb < deg; cb += 32, c++) {
        int len = min(32, deg - cb);
        int myidx;
        float myal;
        if (c < 4) {
            myidx = ic[c];
            myal = en[c] * ri;
        } else {
            myidx = 0; myal = 0.f;
            if (lane < len) {
                myidx = g_csr[base + cb + lane];
                myal = __expf(lrelu(g_as2[myidx] + ad, NEG_ATT)) * ri;
            }
        }
        int j = 0;
        for (; j + 4 <= len; j += 4) {
            int s0 = __shfl_sync(0xffffffffu, myidx, j);
            int s1 = __shfl_sync(0xffffffffu, myidx, j + 1);
            int s2 = __shfl_sync(0xffffffffu, myidx, j + 2);
            int s3 = __shfl_sync(0xffffffffu, myidx, j + 3);
            float a0 = __shfl_sync(0xffffffffu, myal, j);
            float a1 = __shfl_sync(0xffffffffu, myal, j + 1);
            float a2 = __shfl_sync(0xffffffffu, myal, j + 2);
            float a3 = __shfl_sync(0xffffffffu, myal, j + 3);
            float2 f0 = __half22float2(g_h2h[s0 * (C2 / 2) + lane]);
            float2 f1 = __half22float2(g_h2h[s1 * (C2 / 2) + lane]);
            float2 f2 = __half22float2(g_h2h[s2 * (C2 / 2) + lane]);
            float2 f3 = __half22float2(g_h2h[s3 * (C2 / 2) + lane]);
            ax = fmaf(a0, f0.x, ax); ay = fmaf(a0, f0.y, ay);
            ax = fmaf(a1, f1.x, ax); ay = fmaf(a1, f1.y, ay);
            ax = fmaf(a2, f2.x, ax); ay = fmaf(a2, f2.y, ay);
            ax = fmaf(a3, f3.x, ax); ay = fmaf(a3, f3.y, ay);
        }
        for (; j < len; j++) {
            int s = __shfl_sync(0xffffffffu, myidx, j);
            float a = __shfl_sync(0xffffffffu, myal, j);
            float2 f = __half22float2(g_h2h[s * (C2 / 2) + lane]);
            ax = fmaf(a, f.x, ax); ay = fmaf(a, f.y, ay);
        }
    }
    float2 bb = *(const float2*)&b2[2 * lane];
    *(float2*)&out[n * C2 + 2 * lane] = make_float2(ax + bb.x, ay + bb.y);
}

// ---------------- launch -----------------------------------------------------
extern "C" void kernel_launch(void* const* d_in, const int* in_sizes, int n_in,
                              void* d_out, int out_size) {
    const float* x      = (const float*)d_in[0];
    const int*   ei     = (const int*)d_in[1];
    const float* W1     = (const float*)d_in[2];
    const float* a_src1 = (const float*)d_in[3];
    const float* a_dst1 = (const float*)d_in[4];
    const float* b1     = (const float*)d_in[5];
    const float* gamma  = (const float*)d_in[6];
    const float* beta   = (const float*)d_in[7];
    const float* W2     = (const float*)d_in[8];
    const float* a_src2 = (const float*)d_in[9];
    const float* a_dst2 = (const float*)d_in[10];
    const float* b2     = (const float*)d_in[11];
    float* out = (float*)d_out;

    const int4* src4 = (const int4*)ei;
    const int4* dst4 = (const int4*)(ei + EE);

    // one-time host-side stream/event setup (host objects, no device memory)
    static cudaStream_t s2 = nullptr;
    static cudaEvent_t evA = nullptr, evB = nullptr;
    if (s2 == nullptr) {
        cudaStreamCreateWithFlags(&s2, cudaStreamNonBlocking);
        cudaEventCreateWithFlags(&evA, cudaEventDisableTiming);
        cudaEventCreateWithFlags(&evB, cudaEventDisableTiming);
    }

    // fork: branch B (weights + GEMM1) runs concurrently with CSR build
    cudaEventRecord(evA, 0);
    cudaStreamWaitEvent(s2, evA, 0);
    k_prep_w<<<48, 256, 0, s2>>>(W1, W2);
    k_gemm1<<<dim3((NN + 127) / 128, 2), 256, 0, s2>>>(x, a_src1, a_dst1);
    cudaEventRecord(evB, s2);

    // branch A (capture stream): CSR build
    k_init<<<(NN + 255) / 256, 256>>>();
    k_hist<<<(EE / 4 + 255) / 256, 256>>>(dst4);
    k_scan_block<<<(NN + 1023) / 1024, 1024>>>();
    k_scan_finish<<<(NN + 255) / 256, 256>>>();
    k_scatter<<<(EE / 4 + 255) / 256, 256>>>(src4, dst4);

    // join: gat1 needs CSR (branch A) + h1/as1/ad1 (branch B)
    cudaStreamWaitEvent(0, evB, 0);
    k_gat1<<<(NN + 3) / 4, 128>>>(b1);

    // BatchNorm (partial + fused finalize)
    k_bn<<<256, 128>>>(gamma, beta);

    // Layer 2 (BN+leaky fused into GEMM2 load; softmax fused into gat2)
    k_gemm2<<<(NN + 127) / 128, 256>>>(a_src2, a_dst2);
    k_gat2<<<(NN + 3) / 4, 128>>>(b2, out);
}

// round 17
// speedup vs baseline: 1.3760x; 1.3760x over previous
#include <cuda_runtime.h>
#include <cuda_bf16.h>
#include <cuda_fp16.h>
#include <math.h>
#include <stdint.h>

#define NN 50000
#define EE 800000
#define FIN 128
#define HC 256      // HEADS*HID = 4*64
#define HEADS 4
#define HID 64
#define C2 64       // CLASSES
#define ETOT (EE + NN)
#define NEG_ATT 0.2f
#define NEG_ACT 0.01f
#define BN_EPS 1e-5f

// ---------------- scratch (device globals; no allocation allowed) ------------
__device__ int   g_counts[NN];
__device__ int   g_incl[NN];
__device__ int   g_bsum[64];
__device__ int   g_offs[NN + 1];
__device__ int   g_cursor[NN];
__device__ int   g_csr[ETOT];

__device__ __half2 g_h1h[NN * (HC / 2)];   // x @ W1 as fp16 pairs (gather input)
__device__ __half2 g_h2h[NN * (C2 / 2)];   // hn @ W2 as fp16 pairs
__device__ __half2 g_agg1h[NN * (HC / 2)]; // GAT1 output (+b1), fp16
__device__ float g_as1[NN * HEADS];
__device__ float g_ad1[NN * HEADS];
__device__ float g_bnsum[HC];
__device__ float g_bnsq[HC];
__device__ float g_scale[HC];
__device__ float g_shift[HC];
__device__ float g_as2[NN];
__device__ float g_ad2[NN];
__device__ int   g_bncnt;

// W fragments, fragment-linear: W1: [nhalf(2)][khalf(2)][nt(16)][kt(4)][lane(32)] uint4
__device__ uint4 g_wf1[2 * 2 * 16 * 4 * 32];   // 8192
// W2: [kq(4)][nt(8)][kt(4)][lane(32)] uint4
__device__ uint4 g_wf2[4 * 8 * 4 * 32];        // 4096

__device__ __forceinline__ float lrelu(float v, float s) { return v > 0.f ? v : s * v; }

__device__ __forceinline__ uint32_t pack_bf(float a, float b) {
    __nv_bfloat16 ba = __float2bfloat16(a);
    __nv_bfloat16 bb = __float2bfloat16(b);
    uint16_t ua = *(uint16_t*)&ba;
    uint16_t ub = *(uint16_t*)&bb;
    return (uint32_t)ua | ((uint32_t)ub << 16);
}

// split a float2 into bf16 hi pair + bf16 lo-residual pair
__device__ __forceinline__ void split2(float2 u, uint32_t& hi, uint32_t& lo) {
    float hx = __bfloat162float(__float2bfloat16(u.x));
    float hy = __bfloat162float(__float2bfloat16(u.y));
    hi = pack_bf(hx, hy);
    lo = pack_bf(u.x - hx, u.y - hy);
}

__device__ __forceinline__ void mma16816(float* c, uint32_t a0, uint32_t a1,
                                         uint32_t a2, uint32_t a3,
                                         uint32_t b0, uint32_t b1) {
    asm volatile(
        "mma.sync.aligned.m16n8k16.row.col.f32.bf16.bf16.f32 "
        "{%0,%1,%2,%3}, {%4,%5,%6,%7}, {%8,%9}, {%0,%1,%2,%3};\n"
        : "+f"(c[0]), "+f"(c[1]), "+f"(c[2]), "+f"(c[3])
        : "r"(a0), "r"(a1), "r"(a2), "r"(a3), "r"(b0), "r"(b1));
}

__device__ __forceinline__ float4 e4(float4 a, float4 ad) {
    float4 e;
    e.x = __expf(lrelu(a.x + ad.x, NEG_ATT));
    e.y = __expf(lrelu(a.y + ad.y, NEG_ATT));
    e.z = __expf(lrelu(a.z + ad.z, NEG_ATT));
    e.w = __expf(lrelu(a.w + ad.w, NEG_ATT));
    return e;
}

// ---------------- CSR build --------------------------------------------------
__global__ void k_init() {
    int i = blockIdx.x * blockDim.x + threadIdx.x;
    if (i < NN) g_counts[i] = 1;          // self loop pre-counted
    if (i < HC) { g_bnsum[i] = 0.f; g_bnsq[i] = 0.f; }
    if (i == 0) g_bncnt = 0;
}

__global__ void k_hist(const int* __restrict__ dst) {
    int e = blockIdx.x * blockDim.x + threadIdx.x;
    if (e < EE) atomicAdd(&g_counts[dst[e]], 1);
}

__global__ void k_scan_block() {   // grid 49, 1024 threads
    __shared__ int sd[1024];
    int t = threadIdx.x;
    int i = blockIdx.x * 1024 + t;
    int v = (i < NN) ? g_counts[i] : 0;
    sd[t] = v;
    __syncthreads();
    for (int off = 1; off < 1024; off <<= 1) {
        int add = (t >= off) ? sd[t - off] : 0;
        __syncthreads();
        sd[t] += add;
        __syncthreads();
    }
    if (i < NN) g_incl[i] = sd[t];
    if (t == 1023) g_bsum[blockIdx.x] = sd[1023];
}

// finish scan (warp-parallel prefix), insert self-loop at slot 0, set cursor
__global__ void k_scan_finish() {
    __shared__ int s_pref;
    int b = blockIdx.x;
    int t = threadIdx.x;
    int i = b * 256 + t;
    int chunk = b >> 2;        // all 256 indices share i>>10; chunk <= 48
    if (t < 32) {
        int v = (t < chunk) ? g_bsum[t] : 0;
        if (t + 32 < chunk) v += g_bsum[t + 32];
#pragma unroll
        for (int off = 16; off > 0; off >>= 1)
            v += __shfl_xor_sync(0xffffffffu, v, off);
        if (t == 0) s_pref = v;
    }
    __syncthreads();
    if (i < NN) {
        int incl = g_incl[i] + s_pref;
        g_offs[i + 1] = incl;
        int start = incl - g_counts[i];
        g_csr[start] = i;          // self loop occupies first slot
        g_cursor[i] = start + 1;
        if (i == 0) g_offs[0] = 0;
    }
}

__global__ void k_scatter(const int* __restrict__ src, const int* __restrict__ dst) {
    int e = blockIdx.x * blockDim.x + threadIdx.x;
    if (e < EE) {
        int d = dst[e];
        int pos = atomicAdd(&g_cursor[d], 1);
        g_csr[pos] = src[e];
    }
}

// ---------------- W fragment prep (both weights, one launch) -----------------
__global__ void k_prep_w(const float* __restrict__ W1f, const float* __restrict__ W2f) {
    int i = blockIdx.x * blockDim.x + threadIdx.x;
    if (i < 8192) {
        int lane = i & 31;
        int kt = (i >> 5) & 3;
        int nt = (i >> 7) & 15;
        int kh = (i >> 11) & 1;
        int nh = (i >> 12) & 1;
        int g = lane >> 2, q = lane & 3;
        int k = kh * 64 + kt * 16 + 2 * q;
        int n = nh * 128 + nt * 8 + g;
        float w00 = W1f[k * HC + n];
        float w01 = W1f[(k + 1) * HC + n];
        float w10 = W1f[(k + 8) * HC + n];
        float w11 = W1f[(k + 9) * HC + n];
        float h00 = __bfloat162float(__float2bfloat16(w00));
        float h01 = __bfloat162float(__float2bfloat16(w01));
        float h10 = __bfloat162float(__float2bfloat16(w10));
        float h11 = __bfloat162float(__float2bfloat16(w11));
        g_wf1[i] = make_uint4(pack_bf(h00, h01), pack_bf(h10, h11),
                              pack_bf(w00 - h00, w01 - h01), pack_bf(w10 - h10, w11 - h11));
    } else if (i < 8192 + 4096) {
        int j = i - 8192;
        int lane = j & 31;
        int kt = (j >> 5) & 3;
        int nt = (j >> 7) & 7;
        int kq = (j >> 10) & 3;
        int g = lane >> 2, q = lane & 3;
        int k = kq * 64 + kt * 16 + 2 * q;
        int n = nt * 8 + g;
        float w00 = W2f[k * C2 + n];
        float w01 = W2f[(k + 1) * C2 + n];
        float w10 = W2f[(k + 8) * C2 + n];
        float w11 = W2f[(k + 9) * C2 + n];
        float h00 = __bfloat162float(__float2bfloat16(w00));
        float h01 = __bfloat162float(__float2bfloat16(w01));
        float h10 = __bfloat162float(__float2bfloat16(w10));
        float h11 = __bfloat162float(__float2bfloat16(w11));
        g_wf2[j] = make_uint4(pack_bf(h00, h01), pack_bf(h10, h11),
                              pack_bf(w00 - h00, w01 - h01), pack_bf(w10 - h10, w11 - h11));
    }
}

// ---------------- GEMM1: h1 = x @ W1, fp16 store + alpha1 epilogue ----------
// grid (391, 2), 256 threads. Warp w: rows [bx*128+w*16, +16), cols nh*128..+128
__global__ __launch_bounds__(256) void k_gemm1(const float* __restrict__ x,
                                               const float* __restrict__ a_src,
                                               const float* __restrict__ a_dst) {
    __shared__ uint4 bs[16][4][32];    // 32 KB
    int t = threadIdx.x;
    int w = t >> 5, lane = t & 31;
    int g = lane >> 2, q = lane & 3;
    int m0 = blockIdx.x * 128 + w * 16 + g;
    int m1 = m0 + 8;
    bool v0 = m0 < NN, v1 = m1 < NN;
    int nh = blockIdx.y;

    float acc[16][4];
#pragma unroll
    for (int nt = 0; nt < 16; nt++)
#pragma unroll
        for (int r = 0; r < 4; r++) acc[nt][r] = 0.f;

    for (int kh = 0; kh < 2; kh++) {
        const uint4* srcw = g_wf1 + (nh * 2 + kh) * 2048;
        for (int i = t; i < 2048; i += 256) ((uint4*)bs)[i] = srcw[i];
        __syncthreads();
#pragma unroll
        for (int kt = 0; kt < 4; kt++) {
            int kk = kh * 64 + kt * 16 + 2 * q;
            uint32_t ah0 = 0, ah1 = 0, ah2 = 0, ah3 = 0;
            uint32_t al0 = 0, al1 = 0, al2 = 0, al3 = 0;
            if (v0) {
                split2(*(const float2*)&x[m0 * FIN + kk], ah0, al0);
                split2(*(const float2*)&x[m0 * FIN + kk + 8], ah2, al2);
            }
            if (v1) {
                split2(*(const float2*)&x[m1 * FIN + kk], ah1, al1);
                split2(*(const float2*)&x[m1 * FIN + kk + 8], ah3, al3);
            }
#pragma unroll
            for (int nt = 0; nt < 16; nt++) {
                uint4 b = bs[nt][kt][lane];
                mma16816(acc[nt], ah0, ah1, ah2, ah3, b.x, b.y);  // hi*hi
                mma16816(acc[nt], ah0, ah1, ah2, ah3, b.z, b.w);  // hi*lo
                mma16816(acc[nt], al0, al1, al2, al3, b.x, b.y);  // lo*hi
            }
        }
        __syncthreads();
    }
    int nbase = nh * 128;
#pragma unroll
    for (int nt = 0; nt < 16; nt++) {
        int hidx = (nbase >> 1) + nt * 4 + q;
        if (v0) g_h1h[m0 * (HC / 2) + hidx] = __float22half2_rn(make_float2(acc[nt][0], acc[nt][1]));
        if (v1) g_h1h[m1 * (HC / 2) + hidx] = __float22half2_rn(make_float2(acc[nt][2], acc[nt][3]));
    }

    // fused alpha: per-head dot with a_src / a_dst (heads align with nt groups)
    float ps[2][2] = {{0.f, 0.f}, {0.f, 0.f}};
    float pd[2][2] = {{0.f, 0.f}, {0.f, 0.f}};
#pragma unroll
    for (int nt = 0; nt < 16; nt++) {
        int hl = nt >> 3;
        int c0 = nbase + nt * 8 + 2 * q;
        float s0 = a_src[c0], s1 = a_src[c0 + 1];
        float d0 = a_dst[c0], d1 = a_dst[c0 + 1];
        ps[hl][0] += acc[nt][0] * s0 + acc[nt][1] * s1;
        pd[hl][0] += acc[nt][0] * d0 + acc[nt][1] * d1;
        ps[hl][1] += acc[nt][2] * s0 + acc[nt][3] * s1;
        pd[hl][1] += acc[nt][2] * d0 + acc[nt][3] * d1;
    }
#pragma unroll
    for (int off = 1; off <= 2; off <<= 1) {
#pragma unroll
        for (int hl = 0; hl < 2; hl++) {
            ps[hl][0] += __shfl_xor_sync(0xffffffffu, ps[hl][0], off);
            ps[hl][1] += __shfl_xor_sync(0xffffffffu, ps[hl][1], off);
            pd[hl][0] += __shfl_xor_sync(0xffffffffu, pd[hl][0], off);
            pd[hl][1] += __shfl_xor_sync(0xffffffffu, pd[hl][1], off);
        }
    }
    if (q == 0) {
#pragma unroll
        for (int hl = 0; hl < 2; hl++) {
            int gh = nh * 2 + hl;
            if (v0) { g_as1[m0 * 4 + gh] = ps[hl][0]; g_ad1[m0 * 4 + gh] = pd[hl][0]; }
            if (v1) { g_as1[m1 * 4 + gh] = ps[hl][1]; g_ad1[m1 * 4 + gh] = pd[hl][1]; }
        }
    }
}

// ---------------- GAT layer 1: warp/node fused softmax + aggregate -----------
// Each warp handles one node; lane owns 8 channels [lane*8, lane*8+8).
// shfl broadcast of edge idx + per-head alpha; 4-edge unrolled gather.
__global__ __launch_bounds__(128) void k_gat1(const float* __restrict__ b1) {
    int w = threadIdx.x >> 5, lane = threadIdx.x & 31;
    int n = blockIdx.x * 4 + w;
    if (n >= NN) return;
    int base = g_offs[n], deg = g_offs[n + 1] - base;
    float4 ad = ((const float4*)g_ad1)[n];
    int myh = lane >> 3;                 // head for channels lane*8..lane*8+7

    // softmax phase: register-cached exp for deg<=128
    int ic[4];
    float4 ec[4];
    float4 sm = make_float4(0.f, 0.f, 0.f, 0.f);
#pragma unroll
    for (int c = 0; c < 4; c++) {
        int j = lane + c * 32;
        ic[c] = 0;
        ec[c] = make_float4(0.f, 0.f, 0.f, 0.f);
        if (j < deg) {
            ic[c] = g_csr[base + j];
            ec[c] = e4(((const float4*)g_as1)[ic[c]], ad);
            sm.x += ec[c].x; sm.y += ec[c].y; sm.z += ec[c].z; sm.w += ec[c].w;
        }
    }
    for (int j = lane + 128; j < deg; j += 32) {   // rare tail
        int s = g_csr[base + j];
        float4 e = e4(((const float4*)g_as1)[s], ad);
        sm.x += e.x; sm.y += e.y; sm.z += e.z; sm.w += e.w;
    }
#pragma unroll
    for (int off = 16; off > 0; off >>= 1) {
        sm.x += __shfl_xor_sync(0xffffffffu, sm.x, off);
        sm.y += __shfl_xor_sync(0xffffffffu, sm.y, off);
        sm.z += __shfl_xor_sync(0xffffffffu, sm.z, off);
        sm.w += __shfl_xor_sync(0xffffffffu, sm.w, off);
    }
    float4 rv = make_float4(1.f / sm.x, 1.f / sm.y, 1.f / sm.z, 1.f / sm.w);

    // aggregation: broadcast edge idx + per-head alpha from owner lane
    const uint4* h1u4 = (const uint4*)g_h1h;       // 32 uint4 per node row
    float acc[8];
#pragma unroll
    for (int k = 0; k < 8; k++) acc[k] = 0.f;

    for (int cb = 0, c = 0; cb < deg; cb += 32, c++) {
        int len = min(32, deg - cb);
        int myidx;
        float myal;                      // pre-selected head component
        if (c < 4) {
            myidx = ic[c];
            float ex = (myh == 0) ? ec[c].x : (myh == 1) ? ec[c].y
                     : (myh == 2) ? ec[c].z : ec[c].w;
            float rr = (myh == 0) ? rv.x : (myh == 1) ? rv.y
                     : (myh == 2) ? rv.z : rv.w;
            myal = ex * rr;
        } else {
            myidx = 0; myal = 0.f;
            if (lane < len) {
                myidx = g_csr[base + cb + lane];
                float4 e = e4(((const float4*)g_as1)[myidx], ad);
                float ex = (myh == 0) ? e.x : (myh == 1) ? e.y
                         : (myh == 2) ? e.z : e.w;
                float rr = (myh == 0) ? rv.x : (myh == 1) ? rv.y
                         : (myh == 2) ? rv.z : rv.w;
                myal = ex * rr;
            }
        }
        // NOTE: myal holds head (lane>>3) of edge `lane`; the consumer below
        // needs head (its own lane>>3) of edge j — so broadcast from the lane
        // in OUR quarter that owns edge j's alpha for OUR head:
        // source lane = (myh*8 is wrong; alpha for edge j head h lives in lane j
        // component h). Since components differ per head, broadcast all 4:
        // fall back to broadcasting from lane j, all four components, as before.
        // To keep per-edge shfl count at 5 (idx + 4 comps) exactly as the
        // 222 µs baseline, re-derive the full float4 here:
        float4 mya;
        if (c < 4) {
            mya = make_float4(ec[c].x * rv.x, ec[c].y * rv.y,
                              ec[c].z * rv.z, ec[c].w * rv.w);
        } else {
            mya = make_float4(0.f, 0.f, 0.f, 0.f);
            if (lane < len) {
                float4 e = e4(((const float4*)g_as1)[myidx], ad);
                mya = make_float4(e.x * rv.x, e.y * rv.y, e.z * rv.z, e.w * rv.w);
            }
        }
        (void)myal;
        int j = 0;
        for (; j + 4 <= len; j += 4) {
            int s0 = __shfl_sync(0xffffffffu, myidx, j);
            int s1 = __shfl_sync(0xffffffffu, myidx, j + 1);
            int s2 = __shfl_sync(0xffffffffu, myidx, j + 2);
            int s3 = __shfl_sync(0xffffffffu, myidx, j + 3);
            uint4 v0 = h1u4[s0 * 32 + lane];
            uint4 v1 = h1u4[s1 * 32 + lane];
            uint4 v2 = h1u4[s2 * 32 + lane];
            uint4 v3 = h1u4[s3 * 32 + lane];
            float a0x = __shfl_sync(0xffffffffu, mya.x, j);
            float a0y = __shfl_sync(0xffffffffu, mya.y, j);
            float a0z = __shfl_sync(0xffffffffu, mya.z, j);
            float a0w = __shfl_sync(0xffffffffu, mya.w, j);
            float a1x = __shfl_sync(0xffffffffu, mya.x, j + 1);
            float a1y = __shfl_sync(0xffffffffu, mya.y, j + 1);
            float a1z = __shfl_sync(0xffffffffu, mya.z, j + 1);
            float a1w = __shfl_sync(0xffffffffu, mya.w, j + 1);
            float a2x = __shfl_sync(0xffffffffu, mya.x, j + 2);
            float a2y = __shfl_sync(0xffffffffu, mya.y, j + 2);
            float a2z = __shfl_sync(0xffffffffu, mya.z, j + 2);
            float a2w = __shfl_sync(0xffffffffu, mya.w, j + 2);
            float a3x = __shfl_sync(0xffffffffu, mya.x, j + 3);
            float a3y = __shfl_sync(0xffffffffu, mya.y, j + 3);
            float a3z = __shfl_sync(0xffffffffu, mya.z, j + 3);
            float a3w = __shfl_sync(0xffffffffu, mya.w, j + 3);
            float aa0 = (myh == 0) ? a0x : (myh == 1) ? a0y : (myh == 2) ? a0z : a0w;
            float aa1 = (myh == 0) ? a1x : (myh == 1) ? a1y : (myh == 2) ? a1z : a1w;
            float aa2 = (myh == 0) ? a2x : (myh == 1) ? a2y : (myh == 2) ? a2z : a2w;
            float aa3 = (myh == 0) ? a3x : (myh == 1) ? a3y : (myh == 2) ? a3z : a3w;
            float2 p;
            p = __half22float2(*(__half2*)&v0.x); acc[0] = fmaf(aa0, p.x, acc[0]); acc[1] = fmaf(aa0, p.y, acc[1]);
            p = __half22float2(*(__half2*)&v0.y); acc[2] = fmaf(aa0, p.x, acc[2]); acc[3] = fmaf(aa0, p.y, acc[3]);
            p = __half22float2(*(__half2*)&v0.z); acc[4] = fmaf(aa0, p.x, acc[4]); acc[5] = fmaf(aa0, p.y, acc[5]);
            p = __half22float2(*(__half2*)&v0.w); acc[6] = fmaf(aa0, p.x, acc[6]); acc[7] = fmaf(aa0, p.y, acc[7]);
            p = __half22float2(*(__half2*)&v1.x); acc[0] = fmaf(aa1, p.x, acc[0]); acc[1] = fmaf(aa1, p.y, acc[1]);
            p = __half22float2(*(__half2*)&v1.y); acc[2] = fmaf(aa1, p.x, acc[2]); acc[3] = fmaf(aa1, p.y, acc[3]);
            p = __half22float2(*(__half2*)&v1.z); acc[4] = fmaf(aa1, p.x, acc[4]); acc[5] = fmaf(aa1, p.y, acc[5]);
            p = __half22float2(*(__half2*)&v1.w); acc[6] = fmaf(aa1, p.x, acc[6]); acc[7] = fmaf(aa1, p.y, acc[7]);
            p = __half22float2(*(__half2*)&v2.x); acc[0] = fmaf(aa2, p.x, acc[0]); acc[1] = fmaf(aa2, p.y, acc[1]);
            p = __half22float2(*(__half2*)&v2.y); acc[2] = fmaf(aa2, p.x, acc[2]); acc[3] = fmaf(aa2, p.y, acc[3]);
            p = __half22float2(*(__half2*)&v2.z); acc[4] = fmaf(aa2, p.x, acc[4]); acc[5] = fmaf(aa2, p.y, acc[5]);
            p = __half22float2(*(__half2*)&v2.w); acc[6] = fmaf(aa2, p.x, acc[6]); acc[7] = fmaf(aa2, p.y, acc[7]);
            p = __half22float2(*(__half2*)&v3.x); acc[0] = fmaf(aa3, p.x, acc[0]); acc[1] = fmaf(aa3, p.y, acc[1]);
            p = __half22float2(*(__half2*)&v3.y); acc[2] = fmaf(aa3, p.x, acc[2]); acc[3] = fmaf(aa3, p.y, acc[3]);
            p = __half22float2(*(__half2*)&v3.z); acc[4] = fmaf(aa3, p.x, acc[4]); acc[5] = fmaf(aa3, p.y, acc[5]);
            p = __half22float2(*(__half2*)&v3.w); acc[6] = fmaf(aa3, p.x, acc[6]); acc[7] = fmaf(aa3, p.y, acc[7]);
        }
        for (; j < len; j++) {
            int s0 = __shfl_sync(0xffffffffu, myidx, j);
            float a0x = __shfl_sync(0xffffffffu, mya.x, j);
            float a0y = __shfl_sync(0xffffffffu, mya.y, j);
            float a0z = __shfl_sync(0xffffffffu, mya.z, j);
            float a0w = __shfl_sync(0xffffffffu, mya.w, j);
            float aa0 = (myh == 0) ? a0x : (myh == 1) ? a0y : (myh == 2) ? a0z : a0w;
            uint4 v0 = h1u4[s0 * 32 + lane];
            float2 p;
            p = __half22float2(*(__half2*)&v0.x); acc[0] = fmaf(aa0, p.x, acc[0]); acc[1] = fmaf(aa0, p.y, acc[1]);
            p = __half22float2(*(__half2*)&v0.y); acc[2] = fmaf(aa0, p.x, acc[2]); acc[3] = fmaf(aa0, p.y, acc[3]);
            p = __half22float2(*(__half2*)&v0.z); acc[4] = fmaf(aa0, p.x, acc[4]); acc[5] = fmaf(aa0, p.y, acc[5]);
            p = __half22float2(*(__half2*)&v0.w); acc[6] = fmaf(aa0, p.x, acc[6]); acc[7] = fmaf(aa0, p.y, acc[7]);
        }
    }

    // bias + fp16 store (one uint4 = 4 half2 per lane)
    int cbase = lane * 8;
    __half2 o[4];
#pragma unroll
    for (int k = 0; k < 4; k++) {
        float2 bb = *(const float2*)&b1[cbase + 2 * k];
        o[k] = __float22half2_rn(make_float2(acc[2 * k] + bb.x, acc[2 * k + 1] + bb.y));
    }
    ((uint4*)g_agg1h)[n * 32 + lane] = *(uint4*)o;
}

// ---------------- BatchNorm: partial sums + fused finalize -------------------
__global__ __launch_bounds__(128) void k_bn(const float* __restrict__ gamma,
                                            const float* __restrict__ beta) {
    int t = threadIdx.x;                 // half2 column t → channels 2t, 2t+1
    int b = blockIdx.x;
    const int NBLK = 256;
    const int RPB = (NN + NBLK - 1) / NBLK;  // 196
    int rs = b * RPB, re = min(NN, rs + RPB);
    float sx = 0.f, sy = 0.f, qx = 0.f, qy = 0.f;
    for (int r = rs; r < re; r++) {
        float2 v = __half22float2(g_agg1h[r * (HC / 2) + t]);
        sx += v.x; sy += v.y;
        qx = fmaf(v.x, v.x, qx); qy = fmaf(v.y, v.y, qy);
    }
    atomicAdd(&g_bnsum[2 * t], sx);
    atomicAdd(&g_bnsum[2 * t + 1], sy);
    atomicAdd(&g_bnsq[2 * t], qx);
    atomicAdd(&g_bnsq[2 * t + 1], qy);
    __threadfence();
    __shared__ int s_last;
    __syncthreads();
    if (t == 0) s_last = (atomicAdd(&g_bncnt, 1) == NBLK - 1);
    __syncthreads();
    if (s_last) {
#pragma unroll
        for (int u = 0; u < 2; u++) {
            int c = 2 * t + u;
            float mean = g_bnsum[c] / (float)NN;
            float var = g_bnsq[c] / (float)NN - mean * mean;
            float rstd = rsqrtf(var + BN_EPS);
            float sc = gamma[c] * rstd;
            g_scale[c] = sc;
            g_shift[c] = beta[c] - mean * sc;
        }
    }
}

// ---------------- GEMM2: fused BN+leaky+split load, fp16 store, alpha2 -------
// grid 391, 256 threads. Warp w: rows [bx*128+w*16, +16), all 64 cols.
__global__ __launch_bounds__(256) void k_gemm2(const float* __restrict__ a_src,
                                               const float* __restrict__ a_dst) {
    __shared__ uint4 bs[8][4][32];     // 16 KB
    __shared__ float s_sc[HC], s_sh[HC];
    int t = threadIdx.x;
    int w = t >> 5, lane = t & 31;
    int g = lane >> 2, q = lane & 3;
    int m0 = blockIdx.x * 128 + w * 16 + g;
    int m1 = m0 + 8;
    bool v0 = m0 < NN, v1 = m1 < NN;
    for (int i = t; i < HC; i += 256) { s_sc[i] = g_scale[i]; s_sh[i] = g_shift[i]; }

    float acc[8][4];
#pragma unroll
    for (int nt = 0; nt < 8; nt++)
#pragma unroll
        for (int r = 0; r < 4; r++) acc[nt][r] = 0.f;

    for (int kq = 0; kq < 4; kq++) {
        const uint4* srcw = g_wf2 + kq * 1024;
        for (int i = t; i < 1024; i += 256) ((uint4*)bs)[i] = srcw[i];
        __syncthreads();
#pragma unroll
        for (int kt = 0; kt < 4; kt++) {
            int kk = kq * 64 + kt * 16 + 2 * q;
            float sc0 = s_sc[kk], sh0 = s_sh[kk];
            float sc1 = s_sc[kk + 1], sh1 = s_sh[kk + 1];
            float sc8 = s_sc[kk + 8], sh8 = s_sh[kk + 8];
            float sc9 = s_sc[kk + 9], sh9 = s_sh[kk + 9];
            uint32_t ah0 = 0, ah1 = 0, ah2 = 0, ah3 = 0;
            uint32_t al0 = 0, al1 = 0, al2 = 0, al3 = 0;
            if (v0) {
                float2 u = __half22float2(g_agg1h[m0 * (HC / 2) + (kk >> 1)]);
                float2 v = __half22float2(g_agg1h[m0 * (HC / 2) + ((kk + 8) >> 1)]);
                u.x = lrelu(fmaf(sc0, u.x, sh0), NEG_ACT);
                u.y = lrelu(fmaf(sc1, u.y, sh1), NEG_ACT);
                v.x = lrelu(fmaf(sc8, v.x, sh8), NEG_ACT);
                v.y = lrelu(fmaf(sc9, v.y, sh9), NEG_ACT);
                split2(u, ah0, al0);
                split2(v, ah2, al2);
            }
            if (v1) {
                float2 u = __half22float2(g_agg1h[m1 * (HC / 2) + (kk >> 1)]);
                float2 v = __half22float2(g_agg1h[m1 * (HC / 2) + ((kk + 8) >> 1)]);
                u.x = lrelu(fmaf(sc0, u.x, sh0), NEG_ACT);
                u.y = lrelu(fmaf(sc1, u.y, sh1), NEG_ACT);
                v.x = lrelu(fmaf(sc8, v.x, sh8), NEG_ACT);
                v.y = lrelu(fmaf(sc9, v.y, sh9), NEG_ACT);
                split2(u, ah1, al1);
                split2(v, ah3, al3);
            }
#pragma unroll
            for (int nt = 0; nt < 8; nt++) {
                uint4 b = bs[nt][kt][lane];
                mma16816(acc[nt], ah0, ah1, ah2, ah3, b.x, b.y);
                mma16816(acc[nt], ah0, ah1, ah2, ah3, b.z, b.w);
                mma16816(acc[nt], al0, al1, al2, al3, b.x, b.y);
            }
        }
        __syncthreads();
    }
#pragma unroll
    for (int nt = 0; nt < 8; nt++) {
        int hidx = nt * 4 + q;
        if (v0) g_h2h[m0 * (C2 / 2) + hidx] = __float22half2_rn(make_float2(acc[nt][0], acc[nt][1]));
        if (v1) g_h2h[m1 * (C2 / 2) + hidx] = __float22half2_rn(make_float2(acc[nt][2], acc[nt][3]));
    }

    // fused alpha2 (single head over all 64 cols)
    float ps0 = 0.f, ps1 = 0.f, pd0 = 0.f, pd1 = 0.f;
#pragma unroll
    for (int nt = 0; nt < 8; nt++) {
        int c0 = nt * 8 + 2 * q;
        float s0 = a_src[c0], s1 = a_src[c0 + 1];
        float d0 = a_dst[c0], d1 = a_dst[c0 + 1];
        ps0 += acc[nt][0] * s0 + acc[nt][1] * s1;
        pd0 += acc[nt][0] * d0 + acc[nt][1] * d1;
        ps1 += acc[nt][2] * s0 + acc[nt][3] * s1;
        pd1 += acc[nt][2] * d0 + acc[nt][3] * d1;
    }
#pragma unroll
    for (int off = 1; off <= 2; off <<= 1) {
        ps0 += __shfl_xor_sync(0xffffffffu, ps0, off);
        ps1 += __shfl_xor_sync(0xffffffffu, ps1, off);
        pd0 += __shfl_xor_sync(0xffffffffu, pd0, off);
        pd1 += __shfl_xor_sync(0xffffffffu, pd1, off);
    }
    if (q == 0) {
        if (v0) { g_as2[m0] = ps0; g_ad2[m0] = pd0; }
        if (v1) { g_as2[m1] = ps1; g_ad2[m1] = pd1; }
    }
}

// ---------------- GAT layer 2: warp/node, no-max softmax, reg cache → out ----
__global__ __launch_bounds__(128) void k_gat2(const float* __restrict__ b2,
                                              float* __restrict__ out) {
    int w = threadIdx.x >> 5, lane = threadIdx.x & 31;
    int n = blockIdx.x * 4 + w;
    if (n >= NN) return;
    int base = g_offs[n], deg = g_offs[n + 1] - base;
    float ad = g_ad2[n];

    int ic[4];
    float en[4];
    float sm = 0.f;
#pragma unroll
    for (int c = 0; c < 4; c++) {
        int j = lane + c * 32;
        ic[c] = 0; en[c] = 0.f;
        if (j < deg) {
            ic[c] = g_csr[base + j];
            en[c] = __expf(lrelu(g_as2[ic[c]] + ad, NEG_ATT));
            sm += en[c];
        }
    }
    for (int j = lane + 128; j < deg; j += 32)     // rare tail
        sm += __expf(lrelu(g_as2[g_csr[base + j]] + ad, NEG_ATT));
#pragma unroll
    for (int off = 16; off > 0; off >>= 1)
        sm += __shfl_xor_sync(0xffffffffu, sm, off);
    float ri = 1.f / sm;

    float ax = 0.f, ay = 0.f;
    for (int cb = 0, c = 0; cb < deg; cb += 32, c++) {
        int len = min(32, deg - cb);
        int myidx;
        float myal;
        if (c < 4) {
            myidx = ic[c];
            myal = en[c] * ri;
        } else {
            myidx = 0; myal = 0.f;
            if (lane < len) {
                myidx = g_csr[base + cb + lane];
                myal = __expf(lrelu(g_as2[myidx] + ad, NEG_ATT)) * ri;
            }
        }
        int j = 0;
        for (; j + 4 <= len; j += 4) {
            int s0 = __shfl_sync(0xffffffffu, myidx, j);
            int s1 = __shfl_sync(0xffffffffu, myidx, j + 1);
            int s2 = __shfl_sync(0xffffffffu, myidx, j + 2);
            int s3 = __shfl_sync(0xffffffffu, myidx, j + 3);
            float a0 = __shfl_sync(0xffffffffu, myal, j);
            float a1 = __shfl_sync(0xffffffffu, myal, j + 1);
            float a2 = __shfl_sync(0xffffffffu, myal, j + 2);
            float a3 = __shfl_sync(0xffffffffu, myal, j + 3);
            float2 f0 = __half22float2(g_h2h[s0 * (C2 / 2) + lane]);
            float2 f1 = __half22float2(g_h2h[s1 * (C2 / 2) + lane]);
            float2 f2 = __half22float2(g_h2h[s2 * (C2 / 2) + lane]);
            float2 f3 = __half22float2(g_h2h[s3 * (C2 / 2) + lane]);
            ax = fmaf(a0, f0.x, ax); ay = fmaf(a0, f0.y, ay);
            ax = fmaf(a1, f1.x, ax); ay = fmaf(a1, f1.y, ay);
            ax = fmaf(a2, f2.x, ax); ay = fmaf(a2, f2.y, ay);
            ax = fmaf(a3, f3.x, ax); ay = fmaf(a3, f3.y, ay);
        }
        for (; j < len; j++) {
            int s = __shfl_sync(0xffffffffu, myidx, j);
            float a = __shfl_sync(0xffffffffu, myal, j);
            float2 f = __half22float2(g_h2h[s * (C2 / 2) + lane]);
            ax = fmaf(a, f.x, ax); ay = fmaf(a, f.y, ay);
        }
    }
    float2 bb = *(const float2*)&b2[2 * lane];
    *(float2*)&out[n * C2 + 2 * lane] = make_float2(ax + bb.x, ay + bb.y);
}

// ---------------- launch -----------------------------------------------------
extern "C" void kernel_launch(void* const* d_in, const int* in_sizes, int n_in,
                              void* d_out, int out_size) {
    const float* x      = (const float*)d_in[0];
    const int*   ei     = (const int*)d_in[1];
    const float* W1     = (const float*)d_in[2];
    const float* a_src1 = (const float*)d_in[3];
    const float* a_dst1 = (const float*)d_in[4];
    const float* b1     = (const float*)d_in[5];
    const float* gamma  = (const float*)d_in[6];
    const float* beta   = (const float*)d_in[7];
    const float* W2     = (const float*)d_in[8];
    const float* a_src2 = (const float*)d_in[9];
    const float* a_dst2 = (const float*)d_in[10];
    const float* b2     = (const float*)d_in[11];
    float* out = (float*)d_out;

    const int* src = ei;
    const int* dst = ei + EE;

    // one-time host-side stream/event setup (host objects, no device memory)
    static cudaStream_t s2 = nullptr;
    static cudaEvent_t evA = nullptr, evB = nullptr;
    if (s2 == nullptr) {
        cudaStreamCreateWithFlags(&s2, cudaStreamNonBlocking);
        cudaEventCreateWithFlags(&evA, cudaEventDisableTiming);
        cudaEventCreateWithFlags(&evB, cudaEventDisableTiming);
    }

    // fork: branch B (weights + GEMM1) runs concurrently with CSR build
    cudaEventRecord(evA, 0);
    cudaStreamWaitEvent(s2, evA, 0);
    k_prep_w<<<48, 256, 0, s2>>>(W1, W2);
    k_gemm1<<<dim3((NN + 127) / 128, 2), 256, 0, s2>>>(x, a_src1, a_dst1);
    cudaEventRecord(evB, s2);

    // branch A (capture stream): CSR build
    k_init<<<(NN + 255) / 256, 256>>>();
    k_hist<<<(EE + 255) / 256, 256>>>(dst);
    k_scan_block<<<(NN + 1023) / 1024, 1024>>>();
    k_scan_finish<<<(NN + 255) / 256, 256>>>();
    k_scatter<<<(EE + 255) / 256, 256>>>(src, dst);

    // join: gat1 needs CSR (branch A) + h1/as1/ad1 (branch B)
    cudaStreamWaitEvent(0, evB, 0);
    k_gat1<<<(NN + 3) / 4, 128>>>(b1);

    // BatchNorm (partial + fused finalize)
    k_bn<<<256, 128>>>(gamma, beta);

    // Layer 2 (BN+leaky fused into GEMM2 load; softmax fused into gat2)
    k_gemm2<<<(NN + 127) / 128, 256>>>(a_src2, a_dst2);
    k_gat2<<<(NN + 3) / 4, 128>>>(b2, out);
}